// round 14
// baseline (speedup 1.0000x reference)
#include <cuda_runtime.h>
#include <cuda_bf16.h>
#include <math.h>
#include <stdint.h>

// Problem constants
#define Bn 32
#define Tn 512
#define Dn 768
#define Hn 256
#define Kc 32

// ---------------- scratch (device globals; no allocations allowed) ----------
__device__ float g_pre[16384 * 2048];      // [t*B+b][4H_f | 4H_b]  128 MB
__device__ float g_hcat[32 * 512 * 512];   // [b][t][h_f|h_b] 32 MB
__device__ float g_em[32 * 512 * 32];      // [b][t][k] 2 MB
__device__ float g_bloss[32];              // per-batch (num - logZ)

// bf16 two-way split operands for tensor-core GEMM
__device__ __nv_bfloat16 g_Ah[16384 * 768];
__device__ __nv_bfloat16 g_Al[16384 * 768];
__device__ __nv_bfloat16 g_Wh[2048 * 768];
__device__ __nv_bfloat16 g_Wl[2048 * 768];

// ---------------- helpers ----------------------------------------------------
__device__ __forceinline__ uint32_t s2u(const void* p) {
    uint32_t a;
    asm("{ .reg .u64 t; cvta.to.shared.u64 t, %1; cvt.u32.u64 %0, t; }" : "=r"(a) : "l"(p));
    return a;
}
__device__ __forceinline__ void cpa16(uint32_t dst, const void* src) {
    asm volatile("cp.async.cg.shared.global [%0], [%1], 16;" :: "r"(dst), "l"(src));
}
#define CP_COMMIT() asm volatile("cp.async.commit_group;")
#define CP_WAIT(n)  asm volatile("cp.async.wait_group %0;" :: "n"(n))

#define LDM4(r0, r1, r2, r3, addr) \
    asm volatile("ldmatrix.sync.aligned.m8n8.x4.shared.b16 {%0,%1,%2,%3}, [%4];" \
                 : "=r"(r0), "=r"(r1), "=r"(r2), "=r"(r3) : "r"(addr))

#define MMA16816(d, a, b) \
    asm volatile("mma.sync.aligned.m16n8k16.row.col.f32.bf16.bf16.f32 " \
                 "{%0,%1,%2,%3}, {%4,%5,%6,%7}, {%8,%9}, {%0,%1,%2,%3};" \
                 : "+f"((d)[0]), "+f"((d)[1]), "+f"((d)[2]), "+f"((d)[3]) \
                 : "r"((a)[0]), "r"((a)[1]), "r"((a)[2]), "r"((a)[3]), \
                   "r"((b)[0]), "r"((b)[1]))

// ---------------- Phase A0: split fp32 -> 2x bf16 ---------------------------
__global__ void conv_x_kernel(const float* __restrict__ x) {
    int i4 = blockIdx.x * blockDim.x + threadIdx.x;
    if (i4 >= 16384 * 192) return;
    int i = i4 * 4;
    int r = i / 768, k = i - r * 768;
    int t = r >> 5, b = r & 31;
    float4 v = *(const float4*)(x + ((size_t)b * 512 + t) * 768 + k);
    float vv[4] = {v.x, v.y, v.z, v.w};
#pragma unroll
    for (int j = 0; j < 4; j++) {
        float val = vv[j];
        __nv_bfloat16 h = __float2bfloat16(val);
        g_Ah[i + j] = h;
        g_Al[i + j] = __float2bfloat16(val - __bfloat162float(h));
    }
}

__global__ void conv_w_kernel(const float* __restrict__ Wf, const float* __restrict__ Wb) {
    int i4 = blockIdx.x * blockDim.x + threadIdx.x;
    if (i4 >= 2048 * 192) return;
    int i = i4 * 4;
    int n = i / 768, k = i - n * 768;
    const float* src = (n < 1024) ? (Wf + (size_t)n * 768 + k)
                                  : (Wb + (size_t)(n - 1024) * 768 + k);
    float4 v = *(const float4*)src;
    float vv[4] = {v.x, v.y, v.z, v.w};
#pragma unroll
    for (int j = 0; j < 4; j++) {
        float val = vv[j];
        __nv_bfloat16 h = __float2bfloat16(val);
        g_Wh[i + j] = h;
        g_Wl[i + j] = __float2bfloat16(val - __bfloat162float(h));
    }
}

// ---------------- Phase A: pre = x @ [W_ih_f; W_ih_b]^T + bias --------------
#define STG_E 20480              // bf16 elems per stage (4 arrays * 128*40)
#define ARR_E 5120               // 128*40

__global__ __launch_bounds__(256, 1) void gemm_pre_mma(const float* __restrict__ bf_,
                                                       const float* __restrict__ bb_) {
    extern __shared__ __align__(16) __nv_bfloat16 smem[];
    __shared__ float bias_s[128];
    uint32_t sbase = s2u(smem);

    int tid = threadIdx.x;
    int lane = tid & 31, wid = tid >> 5;
    int wm = wid >> 2, wn = wid & 3;          // 2 x 4 warp grid
    int rowBase = blockIdx.y * 128, colBase = blockIdx.x * 128;

    if (tid < 128)
        bias_s[tid] = (colBase < 1024) ? bf_[colBase + tid] : bb_[colBase - 1024 + tid];

    int lr = tid >> 1, kh = (tid & 1) * 16;
    size_t arowg = (size_t)(rowBase + lr) * 768 + kh;
    size_t browg = (size_t)(colBase + lr) * 768 + kh;
    uint32_t drow = (uint32_t)(lr * 40 + kh) * 2;

    {
        uint32_t st = sbase;
        cpa16(st + 0 * ARR_E * 2 + drow,      g_Ah + arowg);
        cpa16(st + 0 * ARR_E * 2 + drow + 16, g_Ah + arowg + 8);
        cpa16(st + 1 * ARR_E * 2 + drow,      g_Al + arowg);
        cpa16(st + 1 * ARR_E * 2 + drow + 16, g_Al + arowg + 8);
        cpa16(st + 2 * ARR_E * 2 + drow,      g_Wh + browg);
        cpa16(st + 2 * ARR_E * 2 + drow + 16, g_Wh + browg + 8);
        cpa16(st + 3 * ARR_E * 2 + drow,      g_Wl + browg);
        cpa16(st + 3 * ARR_E * 2 + drow + 16, g_Wl + browg + 8);
        CP_COMMIT();
    }

    float acc[4][4][4];
#pragma unroll
    for (int i = 0; i < 4; i++)
#pragma unroll
        for (int j = 0; j < 4; j++)
#pragma unroll
            for (int q = 0; q < 4; q++) acc[i][j][q] = 0.f;

    int grp = lane >> 3, lrow = lane & 7;
    int rofs = lrow + (grp & 1) * 8;
    int cofs = (grp >> 1) * 8;

    for (int kt = 0; kt < 24; kt++) {
        if (kt < 23) {
            int k0 = (kt + 1) * 32;
            uint32_t st = sbase + ((kt + 1) & 1) * STG_E * 2;
            cpa16(st + 0 * ARR_E * 2 + drow,      g_Ah + arowg + k0);
            cpa16(st + 0 * ARR_E * 2 + drow + 16, g_Ah + arowg + k0 + 8);
            cpa16(st + 1 * ARR_E * 2 + drow,      g_Al + arowg + k0);
            cpa16(st + 1 * ARR_E * 2 + drow + 16, g_Al + arowg + k0 + 8);
            cpa16(st + 2 * ARR_E * 2 + drow,      g_Wh + browg + k0);
            cpa16(st + 2 * ARR_E * 2 + drow + 16, g_Wh + browg + k0 + 8);
            cpa16(st + 3 * ARR_E * 2 + drow,      g_Wl + browg + k0);
            cpa16(st + 3 * ARR_E * 2 + drow + 16, g_Wl + browg + k0 + 8);
            CP_COMMIT();
            CP_WAIT(1);
        } else {
            CP_WAIT(0);
        }
        __syncthreads();

        uint32_t st = sbase + (kt & 1) * STG_E * 2;
        uint32_t sAh = st, sAl = st + ARR_E * 2;
        uint32_t sBh = st + 2 * ARR_E * 2, sBl = st + 3 * ARR_E * 2;

#pragma unroll
        for (int kk = 0; kk < 32; kk += 16) {
            uint32_t bh[4][2], bl[4][2];
#pragma unroll
            for (int j2 = 0; j2 < 2; j2++) {
                int nrow = wn * 32 + j2 * 16 + rofs;
                uint32_t addr = sBh + (uint32_t)(nrow * 40 + kk + cofs) * 2;
                LDM4(bh[2 * j2][0], bh[2 * j2 + 1][0], bh[2 * j2][1], bh[2 * j2 + 1][1], addr);
                addr = sBl + (uint32_t)(nrow * 40 + kk + cofs) * 2;
                LDM4(bl[2 * j2][0], bl[2 * j2 + 1][0], bl[2 * j2][1], bl[2 * j2 + 1][1], addr);
            }
#pragma unroll
            for (int im = 0; im < 4; im++) {
                int mrow = wm * 64 + im * 16 + rofs;
                uint32_t a[4], al[4];
                uint32_t addr = sAh + (uint32_t)(mrow * 40 + kk + cofs) * 2;
                LDM4(a[0], a[1], a[2], a[3], addr);
                addr = sAl + (uint32_t)(mrow * 40 + kk + cofs) * 2;
                LDM4(al[0], al[1], al[2], al[3], addr);
#pragma unroll
                for (int in_ = 0; in_ < 4; in_++) {
                    MMA16816(acc[im][in_], a,  bh[in_]);
                    MMA16816(acc[im][in_], a,  bl[in_]);
                    MMA16816(acc[im][in_], al, bh[in_]);
                }
            }
        }
        __syncthreads();
    }

    int crow = lane >> 2, ccol = (lane & 3) * 2;
#pragma unroll
    for (int im = 0; im < 4; im++) {
        int r0 = rowBase + wm * 64 + im * 16 + crow;
#pragma unroll
        for (int in_ = 0; in_ < 4; in_++) {
            int c0loc = wn * 32 + in_ * 8 + ccol;
            int gc = colBase + c0loc;
            float2 v0, v1;
            v0.x = acc[im][in_][0] + bias_s[c0loc];
            v0.y = acc[im][in_][1] + bias_s[c0loc + 1];
            v1.x = acc[im][in_][2] + bias_s[c0loc];
            v1.y = acc[im][in_][3] + bias_s[c0loc + 1];
            *(float2*)(g_pre + (size_t)r0 * 2048 + gc) = v0;
            *(float2*)(g_pre + (size_t)(r0 + 8) * 2048 + gc) = v1;
        }
    }
}

// ---------------- Phase B: LSTM recurrence (cluster-8 DSMEM exchange) -------
// SMEM layout (floats): [hx: 2x128][h_s: 4x260][W_s: 4x32x260]
__device__ __forceinline__ float sigf(float v) { return 1.f / (1.f + __expf(-v)); }

__global__ void __cluster_dims__(8, 1, 1) __launch_bounds__(128, 1)
lstm_rec_kernel(const float* __restrict__ Whf,
                const float* __restrict__ Whb,
                const int* __restrict__ lengths) {
    extern __shared__ float sm[];
    float* hx  = sm;                 // [2 parity][4 batches][32 units]
    float* h_s = sm + 256;           // [4 batches][260 (pad)]
    float* W_s = sm + 256 + 4 * 260; // [4 gates][32 units][260 (pad)]

    int tid = threadIdx.x;
    int bk = blockIdx.x;
    int dir = bk >> 6;
    int grp = (bk >> 3) & 7;
    int sl = bk & 7;                 // == cluster rank
    int u0 = sl * 32;
    int u_loc = tid >> 2;
    int bb = tid & 3;
    int u = u0 + u_loc;
    int b = grp * 4 + bb;
    int len = lengths[b];
    const float* Wh = dir ? Whb : Whf;

    for (int idx = tid; idx < 4 * 32 * 256; idx += 128) {
        int g = idx >> 13;
        int rem = idx & 8191;
        int uu = rem >> 8;
        int k = rem & 255;
        W_s[(g * 32 + uu) * 260 + k] = Wh[((size_t)(g * 256 + u0 + uu)) * 256 + k];
    }
    for (int idx = tid; idx < 4 * 260; idx += 128) h_s[idx] = 0.f;

    // precompute DSMEM peer addresses for the gather (8 values per thread)
    uint32_t hx_u = s2u(sm);
    uint32_t paddr[8];
    int dsto[8];
#pragma unroll
    for (int i = 0; i < 8; i++) {
        int j = tid + i * 128;            // j = bb'*256 + u'
        int bbj = j >> 8, uj = j & 255;
        int slj = uj >> 5, ulj = uj & 31;
        uint32_t local = hx_u + (uint32_t)(bbj * 32 + ulj) * 4u;
        asm("mapa.shared::cluster.u32 %0, %1, %2;"
            : "=r"(paddr[i]) : "r"(local), "r"(slj));
        dsto[i] = bbj * 260 + uj;
    }
    __syncthreads();

    float c = 0.f;
    const float* wp0 = W_s + (0 * 32 + u_loc) * 260;
    const float* wp1 = W_s + (1 * 32 + u_loc) * 260;
    const float* wp2 = W_s + (2 * 32 + u_loc) * 260;
    const float* wp3 = W_s + (3 * 32 + u_loc) * 260;
    const float* hb = h_s + bb * 260;

    // prefetch pre-activations for t = 0
    float n0, n1, n2, n3;
    {
        int tt0 = (dir == 0) ? 0 : ((0 < len) ? (len - 1) : 0);
        const float* pr = g_pre + ((size_t)tt0 * 32 + b) * 2048 + dir * 1024 + u;
        n0 = pr[0]; n1 = pr[256]; n2 = pr[512]; n3 = pr[768];
    }

    for (int t = 0; t < 512; t++) {
        int tt = (dir == 0) ? t : ((t < len) ? (len - 1 - t) : t);
        float a0 = n0, a1 = n1, a2 = n2, a3 = n3;

        // prefetch next step (latency hidden by FFMA loop below)
        {
            int tn = (t + 1 < 512) ? (t + 1) : 511;
            int ttn = (dir == 0) ? tn : ((tn < len) ? (len - 1 - tn) : tn);
            const float* prn = g_pre + ((size_t)ttn * 32 + b) * 2048 + dir * 1024 + u;
            n0 = prn[0]; n1 = prn[256]; n2 = prn[512]; n3 = prn[768];
        }

#pragma unroll 8
        for (int k4 = 0; k4 < 64; k4++) {
            float4 hv = ((const float4*)hb)[k4];
            float4 w0 = ((const float4*)wp0)[k4];
            float4 w1 = ((const float4*)wp1)[k4];
            float4 w2 = ((const float4*)wp2)[k4];
            float4 w3 = ((const float4*)wp3)[k4];
            a0 += hv.x * w0.x + hv.y * w0.y + hv.z * w0.z + hv.w * w0.w;
            a1 += hv.x * w1.x + hv.y * w1.y + hv.z * w1.z + hv.w * w1.w;
            a2 += hv.x * w2.x + hv.y * w2.y + hv.z * w2.z + hv.w * w2.w;
            a3 += hv.x * w3.x + hv.y * w3.y + hv.z * w3.z + hv.w * w3.w;
        }
        c = sigf(a1) * c + sigf(a0) * tanhf(a2);
        float hn = sigf(a3) * tanhf(c);

        g_hcat[((size_t)b * 512 + tt) * 512 + dir * 256 + u] = hn;

        // publish own slice to local SMEM, cluster-barrier, gather peers via DSMEM
        int p = t & 1;
        hx[(p << 7) + bb * 32 + u_loc] = hn;
        asm volatile("barrier.cluster.arrive.aligned;" ::: "memory");
        asm volatile("barrier.cluster.wait.aligned;" ::: "memory");
        uint32_t poff = (uint32_t)(p << 9);   // parity * 128 floats * 4 B
#pragma unroll
        for (int i = 0; i < 8; i++) {
            uint32_t vi;
            asm volatile("ld.shared::cluster.b32 %0, [%1];"
                         : "=r"(vi) : "r"(paddr[i] + poff));
            h_s[dsto[i]] = __uint_as_float(vi);
        }
        __syncthreads();
    }

    // keep SMEM alive until all peers finish their final gather
    asm volatile("barrier.cluster.arrive.aligned;" ::: "memory");
    asm volatile("barrier.cluster.wait.aligned;" ::: "memory");
}

// ---------------- Phase C: emissions = hcat @ W_clf^T + b_clf ---------------
__global__ void emis_kernel(const float* __restrict__ Wclf,
                            const float* __restrict__ bclf) {
    extern __shared__ float smc[];
    float* Wt = smc;              // [512][32] transposed W_clf
    float* hrow = smc + 512 * 32; // [8 warps][512]
    int tid = threadIdx.x;
    for (int idx = tid; idx < 32 * 512; idx += 256) {
        int k = idx >> 9, j = idx & 511;
        Wt[j * 32 + k] = Wclf[idx];
    }
    __syncthreads();
    int w = tid >> 5, lane = tid & 31;
    float bk = bclf[lane];
    float* hs = hrow + w * 512;
    int rend = blockIdx.x * 128 + 128;
    for (int r = blockIdx.x * 128 + w; r < rend; r += 8) {
        const float4* src = (const float4*)(g_hcat + (size_t)r * 512);
#pragma unroll
        for (int i = 0; i < 4; i++) ((float4*)hs)[lane + i * 32] = src[lane + i * 32];
        __syncwarp();
        float acc = bk;
#pragma unroll 8
        for (int j4 = 0; j4 < 128; j4++) {
            float4 h4 = ((const float4*)hs)[j4];
            acc += h4.x * Wt[(j4 * 4 + 0) * 32 + lane] + h4.y * Wt[(j4 * 4 + 1) * 32 + lane]
                 + h4.z * Wt[(j4 * 4 + 2) * 32 + lane] + h4.w * Wt[(j4 * 4 + 3) * 32 + lane];
        }
        g_em[(size_t)r * 32 + lane] = acc;
        __syncwarp();
    }
}

// ---------------- Phase D: CRF NLL (per-batch warp) -------------------------
__global__ void crf_nll_kernel(const int* __restrict__ lengths,
                               const int* __restrict__ targets,
                               const float* __restrict__ start_t,
                               const float* __restrict__ end_t,
                               const float* __restrict__ trans) {
    __shared__ float tr[32 * 33];
    int b = blockIdx.x, lane = threadIdx.x;
    for (int idx = lane; idx < 1024; idx += 32) tr[(idx >> 5) * 33 + (idx & 31)] = trans[idx];
    __syncwarp();
    int len = lengths[b];
    const int* tg = targets + b * 512;

    float part = 0.f;
    for (int t = 1 + lane; t < 512; t += 32)
        if (t < len)
            part += trans[tg[t - 1] * 32 + tg[t]] + g_em[((size_t)b * 512 + t) * 32 + tg[t]];
    for (int off = 16; off; off >>= 1) part += __shfl_down_sync(0xffffffffu, part, off);
    float num = 0.f;
    if (lane == 0)
        num = part + start_t[tg[0]] + g_em[((size_t)b * 512) * 32 + tg[0]] + end_t[tg[len - 1]];

    float alpha = start_t[lane] + g_em[((size_t)b * 512) * 32 + lane];
    for (int t = 1; t < 512; t++) {
        float e = g_em[((size_t)b * 512 + t) * 32 + lane];
        float m = -3.402823e38f;
#pragma unroll
        for (int i = 0; i < 32; i++) {
            float v = __shfl_sync(0xffffffffu, alpha, i) + tr[i * 33 + lane];
            m = fmaxf(m, v);
        }
        float s = 0.f;
#pragma unroll
        for (int i = 0; i < 32; i++) {
            float v = __shfl_sync(0xffffffffu, alpha, i) + tr[i * 33 + lane];
            s += __expf(v - m);
        }
        float nxt = m + __logf(s) + e;
        alpha = (t < len) ? nxt : alpha;
    }
    float v = alpha + end_t[lane];
    float mm = v;
    for (int off = 16; off; off >>= 1) mm = fmaxf(mm, __shfl_xor_sync(0xffffffffu, mm, off));
    float se = __expf(v - mm);
    for (int off = 16; off; off >>= 1) se += __shfl_xor_sync(0xffffffffu, se, off);
    if (lane == 0) g_bloss[b] = num - (mm + __logf(se));
}

__global__ void finalize_loss_kernel(float* out) {
    int lane = threadIdx.x;
    float v = g_bloss[lane];
    for (int off = 16; off; off >>= 1) v += __shfl_down_sync(0xffffffffu, v, off);
    if (lane == 0) out[0] = -v * (1.f / 32.f);
}

// ---------------- Phase E: Viterbi decode (per-batch warp) ------------------
__global__ void viterbi_kernel(const int* __restrict__ lengths,
                               const float* __restrict__ start_t,
                               const float* __restrict__ end_t,
                               const float* __restrict__ trans,
                               float* __restrict__ out) {
    __shared__ float tr[32 * 33];
    __shared__ unsigned char hist[511 * 32];
    int b = blockIdx.x, lane = threadIdx.x;
    for (int idx = lane; idx < 1024; idx += 32) tr[(idx >> 5) * 33 + (idx & 31)] = trans[idx];
    __syncwarp();
    int len = lengths[b];

    float score = start_t[lane] + g_em[((size_t)b * 512) * 32 + lane];
    for (int t = 1; t < 512; t++) {
        float e = g_em[((size_t)b * 512 + t) * 32 + lane];
        float m = -3.402823e38f;
        int arg = 0;
#pragma unroll
        for (int i = 0; i < 32; i++) {
            float v = __shfl_sync(0xffffffffu, score, i) + tr[i * 33 + lane];
            if (v > m) { m = v; arg = i; }
        }
        bool valid = (t < len);
        hist[(t - 1) * 32 + lane] = (unsigned char)(valid ? arg : lane);
        score = valid ? (m + e) : score;
    }
    float bv = score + end_t[lane];
    int bi = lane;
    for (int off = 16; off; off >>= 1) {
        float ov = __shfl_down_sync(0xffffffffu, bv, off);
        int oi = __shfl_down_sync(0xffffffffu, bi, off);
        if (ov > bv || (ov == bv && oi < bi)) { bv = ov; bi = oi; }
    }
    int last = __shfl_sync(0xffffffffu, bi, 0);
    if (lane == 0) {
        int tag = last;
        out[1 + b * 512 + 511] = (511 < len) ? (float)tag : 0.f;
        for (int s = 510; s >= 0; s--) {
            tag = hist[s * 32 + tag];
            out[1 + b * 512 + s] = (s < len) ? (float)tag : 0.f;
        }
    }
}

// ---------------- launch ----------------------------------------------------
extern "C" void kernel_launch(void* const* d_in, const int* in_sizes, int n_in,
                              void* d_out, int out_size) {
    const float* x       = (const float*)d_in[0];
    const int*   lengths = (const int*)  d_in[1];
    const int*   targets = (const int*)  d_in[3];
    const float* W_ih_f  = (const float*)d_in[4];
    const float* W_hh_f  = (const float*)d_in[5];
    const float* b_f     = (const float*)d_in[6];
    const float* W_ih_b  = (const float*)d_in[7];
    const float* W_hh_b  = (const float*)d_in[8];
    const float* b_b     = (const float*)d_in[9];
    const float* W_clf   = (const float*)d_in[10];
    const float* b_clf   = (const float*)d_in[11];
    const float* start_t = (const float*)d_in[12];
    const float* end_t   = (const float*)d_in[13];
    const float* trans   = (const float*)d_in[14];
    float* out = (float*)d_out;

    conv_x_kernel<<<(16384 * 192 + 255) / 256, 256>>>(x);
    conv_w_kernel<<<(2048 * 192 + 255) / 256, 256>>>(W_ih_f, W_ih_b);

    int smem_g = 2 * STG_E * 2;  // 81920 B
    cudaFuncSetAttribute(gemm_pre_mma, cudaFuncAttributeMaxDynamicSharedMemorySize, smem_g);
    dim3 gg(16, 128);
    gemm_pre_mma<<<gg, 256, smem_g>>>(b_f, b_b);

    int smem_rec = (256 + 4 * 260 + 4 * 32 * 260) * 4;  // 138304 B
    cudaFuncSetAttribute(lstm_rec_kernel, cudaFuncAttributeMaxDynamicSharedMemorySize, smem_rec);
    lstm_rec_kernel<<<128, 128, smem_rec>>>(W_hh_f, W_hh_b, lengths);

    int smem_em = (512 * 32 + 8 * 512) * 4;
    cudaFuncSetAttribute(emis_kernel, cudaFuncAttributeMaxDynamicSharedMemorySize, smem_em);
    emis_kernel<<<128, 256, smem_em>>>(W_clf, b_clf);

    crf_nll_kernel<<<32, 32>>>(lengths, targets, start_t, end_t, trans);
    finalize_loss_kernel<<<1, 32>>>(out);
    viterbi_kernel<<<32, 32>>>(lengths, start_t, end_t, trans, out);
}

// round 15
// speedup vs baseline: 1.5180x; 1.5180x over previous
#include <cuda_runtime.h>
#include <cuda_bf16.h>
#include <math.h>
#include <stdint.h>

// Problem constants
#define Bn 32
#define Tn 512
#define Dn 768
#define Hn 256
#define Kc 32

// ---------------- scratch (device globals; no allocations allowed) ----------
__device__ float g_pre[16384 * 2048];      // [t*B+b][4H_f | 4H_b]  128 MB
__device__ float g_hcat[32 * 512 * 512];   // [b][t][h_f|h_b] 32 MB
__device__ float g_em[32 * 512 * 32];      // [b][t][k] 2 MB
__device__ float g_bloss[32];              // per-batch (num - logZ)
__device__ float g_hx2[2 * 2 * 8 * 1024];  // [parity][dir][grp][bb*256+u]
__device__ int   g_flag[2 * 8 * 8 * 32];   // [dir][grp][slice] padded 128B

// bf16 two-way split operands for tensor-core GEMM
__device__ __nv_bfloat16 g_Ah[16384 * 768];
__device__ __nv_bfloat16 g_Al[16384 * 768];
__device__ __nv_bfloat16 g_Wh[2048 * 768];
__device__ __nv_bfloat16 g_Wl[2048 * 768];

// ---------------- helpers ----------------------------------------------------
__device__ __forceinline__ uint32_t s2u(const void* p) {
    uint32_t a;
    asm("{ .reg .u64 t; cvta.to.shared.u64 t, %1; cvt.u32.u64 %0, t; }" : "=r"(a) : "l"(p));
    return a;
}
__device__ __forceinline__ void cpa16(uint32_t dst, const void* src) {
    asm volatile("cp.async.cg.shared.global [%0], [%1], 16;" :: "r"(dst), "l"(src));
}
#define CP_COMMIT() asm volatile("cp.async.commit_group;")
#define CP_WAIT(n)  asm volatile("cp.async.wait_group %0;" :: "n"(n))

#define LDM4(r0, r1, r2, r3, addr) \
    asm volatile("ldmatrix.sync.aligned.m8n8.x4.shared.b16 {%0,%1,%2,%3}, [%4];" \
                 : "=r"(r0), "=r"(r1), "=r"(r2), "=r"(r3) : "r"(addr))

#define MMA16816(d, a, b) \
    asm volatile("mma.sync.aligned.m16n8k16.row.col.f32.bf16.bf16.f32 " \
                 "{%0,%1,%2,%3}, {%4,%5,%6,%7}, {%8,%9}, {%0,%1,%2,%3};" \
                 : "+f"((d)[0]), "+f"((d)[1]), "+f"((d)[2]), "+f"((d)[3]) \
                 : "r"((a)[0]), "r"((a)[1]), "r"((a)[2]), "r"((a)[3]), \
                   "r"((b)[0]), "r"((b)[1]))

// ---------------- init: zero flags (replay-safe) ----------------------------
__global__ void zero_flag_kernel() {
    int i = blockIdx.x * blockDim.x + threadIdx.x;
    if (i < 2 * 8 * 8 * 32) g_flag[i] = 0;
}

// ---------------- Phase A0: split fp32 -> 2x bf16 ---------------------------
__global__ void conv_x_kernel(const float* __restrict__ x) {
    int i4 = blockIdx.x * blockDim.x + threadIdx.x;
    if (i4 >= 16384 * 192) return;
    int i = i4 * 4;
    int r = i / 768, k = i - r * 768;
    int t = r >> 5, b = r & 31;
    float4 v = *(const float4*)(x + ((size_t)b * 512 + t) * 768 + k);
    float vv[4] = {v.x, v.y, v.z, v.w};
#pragma unroll
    for (int j = 0; j < 4; j++) {
        float val = vv[j];
        __nv_bfloat16 h = __float2bfloat16(val);
        g_Ah[i + j] = h;
        g_Al[i + j] = __float2bfloat16(val - __bfloat162float(h));
    }
}

__global__ void conv_w_kernel(const float* __restrict__ Wf, const float* __restrict__ Wb) {
    int i4 = blockIdx.x * blockDim.x + threadIdx.x;
    if (i4 >= 2048 * 192) return;
    int i = i4 * 4;
    int n = i / 768, k = i - n * 768;
    const float* src = (n < 1024) ? (Wf + (size_t)n * 768 + k)
                                  : (Wb + (size_t)(n - 1024) * 768 + k);
    float4 v = *(const float4*)src;
    float vv[4] = {v.x, v.y, v.z, v.w};
#pragma unroll
    for (int j = 0; j < 4; j++) {
        float val = vv[j];
        __nv_bfloat16 h = __float2bfloat16(val);
        g_Wh[i + j] = h;
        g_Wl[i + j] = __float2bfloat16(val - __bfloat162float(h));
    }
}

// ---------------- Phase A: pre = x @ [W_ih_f; W_ih_b]^T + bias --------------
#define STG_E 20480              // bf16 elems per stage (4 arrays * 128*40)
#define ARR_E 5120               // 128*40

__global__ __launch_bounds__(256, 1) void gemm_pre_mma(const float* __restrict__ bf_,
                                                       const float* __restrict__ bb_) {
    extern __shared__ __align__(16) __nv_bfloat16 smem[];
    __shared__ float bias_s[128];
    uint32_t sbase = s2u(smem);

    int tid = threadIdx.x;
    int lane = tid & 31, wid = tid >> 5;
    int wm = wid >> 2, wn = wid & 3;          // 2 x 4 warp grid
    int rowBase = blockIdx.y * 128, colBase = blockIdx.x * 128;

    if (tid < 128)
        bias_s[tid] = (colBase < 1024) ? bf_[colBase + tid] : bb_[colBase - 1024 + tid];

    int lr = tid >> 1, kh = (tid & 1) * 16;
    size_t arowg = (size_t)(rowBase + lr) * 768 + kh;
    size_t browg = (size_t)(colBase + lr) * 768 + kh;
    uint32_t drow = (uint32_t)(lr * 40 + kh) * 2;

    {
        uint32_t st = sbase;
        cpa16(st + 0 * ARR_E * 2 + drow,      g_Ah + arowg);
        cpa16(st + 0 * ARR_E * 2 + drow + 16, g_Ah + arowg + 8);
        cpa16(st + 1 * ARR_E * 2 + drow,      g_Al + arowg);
        cpa16(st + 1 * ARR_E * 2 + drow + 16, g_Al + arowg + 8);
        cpa16(st + 2 * ARR_E * 2 + drow,      g_Wh + browg);
        cpa16(st + 2 * ARR_E * 2 + drow + 16, g_Wh + browg + 8);
        cpa16(st + 3 * ARR_E * 2 + drow,      g_Wl + browg);
        cpa16(st + 3 * ARR_E * 2 + drow + 16, g_Wl + browg + 8);
        CP_COMMIT();
    }

    float acc[4][4][4];
#pragma unroll
    for (int i = 0; i < 4; i++)
#pragma unroll
        for (int j = 0; j < 4; j++)
#pragma unroll
            for (int q = 0; q < 4; q++) acc[i][j][q] = 0.f;

    int grp = lane >> 3, lrow = lane & 7;
    int rofs = lrow + (grp & 1) * 8;
    int cofs = (grp >> 1) * 8;

    for (int kt = 0; kt < 24; kt++) {
        if (kt < 23) {
            int k0 = (kt + 1) * 32;
            uint32_t st = sbase + ((kt + 1) & 1) * STG_E * 2;
            cpa16(st + 0 * ARR_E * 2 + drow,      g_Ah + arowg + k0);
            cpa16(st + 0 * ARR_E * 2 + drow + 16, g_Ah + arowg + k0 + 8);
            cpa16(st + 1 * ARR_E * 2 + drow,      g_Al + arowg + k0);
            cpa16(st + 1 * ARR_E * 2 + drow + 16, g_Al + arowg + k0 + 8);
            cpa16(st + 2 * ARR_E * 2 + drow,      g_Wh + browg + k0);
            cpa16(st + 2 * ARR_E * 2 + drow + 16, g_Wh + browg + k0 + 8);
            cpa16(st + 3 * ARR_E * 2 + drow,      g_Wl + browg + k0);
            cpa16(st + 3 * ARR_E * 2 + drow + 16, g_Wl + browg + k0 + 8);
            CP_COMMIT();
            CP_WAIT(1);
        } else {
            CP_WAIT(0);
        }
        __syncthreads();

        uint32_t st = sbase + (kt & 1) * STG_E * 2;
        uint32_t sAh = st, sAl = st + ARR_E * 2;
        uint32_t sBh = st + 2 * ARR_E * 2, sBl = st + 3 * ARR_E * 2;

#pragma unroll
        for (int kk = 0; kk < 32; kk += 16) {
            uint32_t bh[4][2], bl[4][2];
#pragma unroll
            for (int j2 = 0; j2 < 2; j2++) {
                int nrow = wn * 32 + j2 * 16 + rofs;
                uint32_t addr = sBh + (uint32_t)(nrow * 40 + kk + cofs) * 2;
                LDM4(bh[2 * j2][0], bh[2 * j2 + 1][0], bh[2 * j2][1], bh[2 * j2 + 1][1], addr);
                addr = sBl + (uint32_t)(nrow * 40 + kk + cofs) * 2;
                LDM4(bl[2 * j2][0], bl[2 * j2 + 1][0], bl[2 * j2][1], bl[2 * j2 + 1][1], addr);
            }
#pragma unroll
            for (int im = 0; im < 4; im++) {
                int mrow = wm * 64 + im * 16 + rofs;
                uint32_t a[4], al[4];
                uint32_t addr = sAh + (uint32_t)(mrow * 40 + kk + cofs) * 2;
                LDM4(a[0], a[1], a[2], a[3], addr);
                addr = sAl + (uint32_t)(mrow * 40 + kk + cofs) * 2;
                LDM4(al[0], al[1], al[2], al[3], addr);
#pragma unroll
                for (int in_ = 0; in_ < 4; in_++) {
                    MMA16816(acc[im][in_], a,  bh[in_]);
                    MMA16816(acc[im][in_], a,  bl[in_]);
                    MMA16816(acc[im][in_], al, bh[in_]);
                }
            }
        }
        __syncthreads();
    }

    int crow = lane >> 2, ccol = (lane & 3) * 2;
#pragma unroll
    for (int im = 0; im < 4; im++) {
        int r0 = rowBase + wm * 64 + im * 16 + crow;
#pragma unroll
        for (int in_ = 0; in_ < 4; in_++) {
            int c0loc = wn * 32 + in_ * 8 + ccol;
            int gc = colBase + c0loc;
            float2 v0, v1;
            v0.x = acc[im][in_][0] + bias_s[c0loc];
            v0.y = acc[im][in_][1] + bias_s[c0loc + 1];
            v1.x = acc[im][in_][2] + bias_s[c0loc];
            v1.y = acc[im][in_][3] + bias_s[c0loc + 1];
            *(float2*)(g_pre + (size_t)r0 * 2048 + gc) = v0;
            *(float2*)(g_pre + (size_t)(r0 + 8) * 2048 + gc) = v1;
        }
    }
}

// ---------------- Phase B: LSTM recurrence (flag release/acquire barrier) ---
__device__ __forceinline__ float sigf(float v) { return 1.f / (1.f + __expf(-v)); }

__global__ void __launch_bounds__(128, 1)
lstm_rec_kernel(const float* __restrict__ Whf,
                const float* __restrict__ Whb,
                const int* __restrict__ lengths) {
    extern __shared__ float sm[];
    float* h_s = sm;                 // [4 batches][260 (pad)]
    float* W_s = sm + 4 * 260;       // [4 gates][32 units][260 (pad)]

    int tid = threadIdx.x;
    int bk = blockIdx.x;
    int dir = bk >> 6;
    int grp = (bk >> 3) & 7;
    int sl = bk & 7;
    int u0 = sl * 32;
    int u_loc = tid >> 2;
    int bb = tid & 3;
    int u = u0 + u_loc;
    int b = grp * 4 + bb;
    int len = lengths[b];
    const float* Wh = dir ? Whb : Whf;

    for (int idx = tid; idx < 4 * 32 * 256; idx += 128) {
        int g = idx >> 13;
        int rem = idx & 8191;
        int uu = rem >> 8;
        int k = rem & 255;
        W_s[(g * 32 + uu) * 260 + k] = Wh[((size_t)(g * 256 + u0 + uu)) * 256 + k];
    }
    for (int idx = tid; idx < 4 * 260; idx += 128) h_s[idx] = 0.f;
    __syncthreads();

    int gi = dir * 8 + grp;
    int* myflag = g_flag + (gi * 8 + sl) * 32;
    int* flagbase = g_flag + gi * 8 * 32;

    float c = 0.f;
    const float* wp0 = W_s + (0 * 32 + u_loc) * 260;
    const float* wp1 = W_s + (1 * 32 + u_loc) * 260;
    const float* wp2 = W_s + (2 * 32 + u_loc) * 260;
    const float* wp3 = W_s + (3 * 32 + u_loc) * 260;
    const float* hb = h_s + bb * 260;

    // prefetch pre-activations for t = 0
    float n0, n1, n2, n3;
    {
        int tt0 = (dir == 0) ? 0 : (len - 1);
        const float* pr = g_pre + ((size_t)tt0 * 32 + b) * 2048 + dir * 1024 + u;
        n0 = pr[0]; n1 = pr[256]; n2 = pr[512]; n3 = pr[768];
    }

    for (int t = 0; t < 512; t++) {
        int tt = (dir == 0) ? t : ((t < len) ? (len - 1 - t) : t);
        float a0 = n0, a1 = n1, a2 = n2, a3 = n3;

        // prefetch next step's pre-activations (hidden under FFMA loop)
        {
            int tn = (t + 1 < 512) ? (t + 1) : 511;
            int ttn = (dir == 0) ? tn : ((tn < len) ? (len - 1 - tn) : tn);
            const float* prn = g_pre + ((size_t)ttn * 32 + b) * 2048 + dir * 1024 + u;
            n0 = prn[0]; n1 = prn[256]; n2 = prn[512]; n3 = prn[768];
        }

#pragma unroll 8
        for (int k4 = 0; k4 < 64; k4++) {
            float4 hv = ((const float4*)hb)[k4];
            float4 w0 = ((const float4*)wp0)[k4];
            float4 w1 = ((const float4*)wp1)[k4];
            float4 w2 = ((const float4*)wp2)[k4];
            float4 w3 = ((const float4*)wp3)[k4];
            a0 += hv.x * w0.x + hv.y * w0.y + hv.z * w0.z + hv.w * w0.w;
            a1 += hv.x * w1.x + hv.y * w1.y + hv.z * w1.z + hv.w * w1.w;
            a2 += hv.x * w2.x + hv.y * w2.y + hv.z * w2.z + hv.w * w2.w;
            a3 += hv.x * w3.x + hv.y * w3.y + hv.z * w3.z + hv.w * w3.w;
        }
        c = sigf(a1) * c + sigf(a0) * tanhf(a2);
        float hn = sigf(a3) * tanhf(c);

        int p = t & 1;
        float* hxp = g_hx2 + (size_t)(((p * 2 + dir) * 8 + grp)) * 1024;
        __stcg(&hxp[bb * 256 + u], hn);
        g_hcat[((size_t)b * 512 + tt) * 512 + dir * 256 + u] = hn;
        __syncthreads();   // all hx stores issued before the release publish

        if (tid == 0)
            asm volatile("st.release.gpu.global.b32 [%0], %1;"
                         :: "l"(myflag), "r"(t + 1) : "memory");
        if (tid < 8) {
            int v;
            do {
                asm volatile("ld.acquire.gpu.global.b32 %0, [%1];"
                             : "=r"(v) : "l"(flagbase + tid * 32) : "memory");
            } while (v < t + 1);
        }
        __syncthreads();   // flag acquire visible to whole block

        // gather full h (4 batches x 256 units) for next step
#pragma unroll
        for (int i = 0; i < 8; i++) {
            int j = tid + i * 128;
            h_s[(j >> 8) * 260 + (j & 255)] = __ldcg(&hxp[j]);
        }
        __syncthreads();
    }
}

// ---------------- Phase C: emissions = hcat @ W_clf^T + b_clf ---------------
__global__ void emis_kernel(const float* __restrict__ Wclf,
                            const float* __restrict__ bclf) {
    extern __shared__ float smc[];
    float* Wt = smc;              // [512][32] transposed W_clf
    float* hrow = smc + 512 * 32; // [8 warps][512]
    int tid = threadIdx.x;
    for (int idx = tid; idx < 32 * 512; idx += 256) {
        int k = idx >> 9, j = idx & 511;
        Wt[j * 32 + k] = Wclf[idx];
    }
    __syncthreads();
    int w = tid >> 5, lane = tid & 31;
    float bk = bclf[lane];
    float* hs = hrow + w * 512;
    int rend = blockIdx.x * 128 + 128;
    for (int r = blockIdx.x * 128 + w; r < rend; r += 8) {
        const float4* src = (const float4*)(g_hcat + (size_t)r * 512);
#pragma unroll
        for (int i = 0; i < 4; i++) ((float4*)hs)[lane + i * 32] = src[lane + i * 32];
        __syncwarp();
        float acc = bk;
#pragma unroll 8
        for (int j4 = 0; j4 < 128; j4++) {
            float4 h4 = ((const float4*)hs)[j4];
            acc += h4.x * Wt[(j4 * 4 + 0) * 32 + lane] + h4.y * Wt[(j4 * 4 + 1) * 32 + lane]
                 + h4.z * Wt[(j4 * 4 + 2) * 32 + lane] + h4.w * Wt[(j4 * 4 + 3) * 32 + lane];
        }
        g_em[(size_t)r * 32 + lane] = acc;
        __syncwarp();
    }
}

// ---------------- Phase D: CRF NLL (per-batch warp) -------------------------
__global__ void crf_nll_kernel(const int* __restrict__ lengths,
                               const int* __restrict__ targets,
                               const float* __restrict__ start_t,
                               const float* __restrict__ end_t,
                               const float* __restrict__ trans) {
    __shared__ float tr[32 * 33];
    int b = blockIdx.x, lane = threadIdx.x;
    for (int idx = lane; idx < 1024; idx += 32) tr[(idx >> 5) * 33 + (idx & 31)] = trans[idx];
    __syncwarp();
    int len = lengths[b];
    const int* tg = targets + b * 512;

    float part = 0.f;
    for (int t = 1 + lane; t < 512; t += 32)
        if (t < len)
            part += trans[tg[t - 1] * 32 + tg[t]] + g_em[((size_t)b * 512 + t) * 32 + tg[t]];
    for (int off = 16; off; off >>= 1) part += __shfl_down_sync(0xffffffffu, part, off);
    float num = 0.f;
    if (lane == 0)
        num = part + start_t[tg[0]] + g_em[((size_t)b * 512) * 32 + tg[0]] + end_t[tg[len - 1]];

    float alpha = start_t[lane] + g_em[((size_t)b * 512) * 32 + lane];
    for (int t = 1; t < 512; t++) {
        float e = g_em[((size_t)b * 512 + t) * 32 + lane];
        float m = -3.402823e38f;
#pragma unroll
        for (int i = 0; i < 32; i++) {
            float v = __shfl_sync(0xffffffffu, alpha, i) + tr[i * 33 + lane];
            m = fmaxf(m, v);
        }
        float s = 0.f;
#pragma unroll
        for (int i = 0; i < 32; i++) {
            float v = __shfl_sync(0xffffffffu, alpha, i) + tr[i * 33 + lane];
            s += __expf(v - m);
        }
        float nxt = m + __logf(s) + e;
        alpha = (t < len) ? nxt : alpha;
    }
    float v = alpha + end_t[lane];
    float mm = v;
    for (int off = 16; off; off >>= 1) mm = fmaxf(mm, __shfl_xor_sync(0xffffffffu, mm, off));
    float se = __expf(v - mm);
    for (int off = 16; off; off >>= 1) se += __shfl_xor_sync(0xffffffffu, se, off);
    if (lane == 0) g_bloss[b] = num - (mm + __logf(se));
}

__global__ void finalize_loss_kernel(float* out) {
    int lane = threadIdx.x;
    float v = g_bloss[lane];
    for (int off = 16; off; off >>= 1) v += __shfl_down_sync(0xffffffffu, v, off);
    if (lane == 0) out[0] = -v * (1.f / 32.f);
}

// ---------------- Phase E: Viterbi decode (per-batch warp) ------------------
__global__ void viterbi_kernel(const int* __restrict__ lengths,
                               const float* __restrict__ start_t,
                               const float* __restrict__ end_t,
                               const float* __restrict__ trans,
                               float* __restrict__ out) {
    __shared__ float tr[32 * 33];
    __shared__ unsigned char hist[511 * 32];
    int b = blockIdx.x, lane = threadIdx.x;
    for (int idx = lane; idx < 1024; idx += 32) tr[(idx >> 5) * 33 + (idx & 31)] = trans[idx];
    __syncwarp();
    int len = lengths[b];

    float score = start_t[lane] + g_em[((size_t)b * 512) * 32 + lane];
    for (int t = 1; t < 512; t++) {
        float e = g_em[((size_t)b * 512 + t) * 32 + lane];
        float m = -3.402823e38f;
        int arg = 0;
#pragma unroll
        for (int i = 0; i < 32; i++) {
            float v = __shfl_sync(0xffffffffu, score, i) + tr[i * 33 + lane];
            if (v > m) { m = v; arg = i; }
        }
        bool valid = (t < len);
        hist[(t - 1) * 32 + lane] = (unsigned char)(valid ? arg : lane);
        score = valid ? (m + e) : score;
    }
    float bv = score + end_t[lane];
    int bi = lane;
    for (int off = 16; off; off >>= 1) {
        float ov = __shfl_down_sync(0xffffffffu, bv, off);
        int oi = __shfl_down_sync(0xffffffffu, bi, off);
        if (ov > bv || (ov == bv && oi < bi)) { bv = ov; bi = oi; }
    }
    int last = __shfl_sync(0xffffffffu, bi, 0);
    if (lane == 0) {
        int tag = last;
        out[1 + b * 512 + 511] = (511 < len) ? (float)tag : 0.f;
        for (int s = 510; s >= 0; s--) {
            tag = hist[s * 32 + tag];
            out[1 + b * 512 + s] = (s < len) ? (float)tag : 0.f;
        }
    }
}

// ---------------- launch ----------------------------------------------------
extern "C" void kernel_launch(void* const* d_in, const int* in_sizes, int n_in,
                              void* d_out, int out_size) {
    const float* x       = (const float*)d_in[0];
    const int*   lengths = (const int*)  d_in[1];
    const int*   targets = (const int*)  d_in[3];
    const float* W_ih_f  = (const float*)d_in[4];
    const float* W_hh_f  = (const float*)d_in[5];
    const float* b_f     = (const float*)d_in[6];
    const float* W_ih_b  = (const float*)d_in[7];
    const float* W_hh_b  = (const float*)d_in[8];
    const float* b_b     = (const float*)d_in[9];
    const float* W_clf   = (const float*)d_in[10];
    const float* b_clf   = (const float*)d_in[11];
    const float* start_t = (const float*)d_in[12];
    const float* end_t   = (const float*)d_in[13];
    const float* trans   = (const float*)d_in[14];
    float* out = (float*)d_out;

    zero_flag_kernel<<<16, 256>>>();

    conv_x_kernel<<<(16384 * 192 + 255) / 256, 256>>>(x);
    conv_w_kernel<<<(2048 * 192 + 255) / 256, 256>>>(W_ih_f, W_ih_b);

    int smem_g = 2 * STG_E * 2;  // 81920 B
    cudaFuncSetAttribute(gemm_pre_mma, cudaFuncAttributeMaxDynamicSharedMemorySize, smem_g);
    dim3 gg(16, 128);
    gemm_pre_mma<<<gg, 256, smem_g>>>(b_f, b_b);

    int smem_rec = (4 * 260 + 4 * 32 * 260) * 4;  // 137280 B
    cudaFuncSetAttribute(lstm_rec_kernel, cudaFuncAttributeMaxDynamicSharedMemorySize, smem_rec);
    lstm_rec_kernel<<<128, 128, smem_rec>>>(W_hh_f, W_hh_b, lengths);

    int smem_em = (512 * 32 + 8 * 512) * 4;
    cudaFuncSetAttribute(emis_kernel, cudaFuncAttributeMaxDynamicSharedMemorySize, smem_em);
    emis_kernel<<<128, 256, smem_em>>>(W_clf, b_clf);

    crf_nll_kernel<<<32, 32>>>(lengths, targets, start_t, end_t, trans);
    finalize_loss_kernel<<<1, 32>>>(out);
    viterbi_kernel<<<32, 32>>>(lengths, start_t, end_t, trans, out);
}